// round 16
// baseline (speedup 1.0000x reference)
#include <cuda_runtime.h>
#include <cuda_bf16.h>
#include <math.h>
#include <stdint.h>

#define A_TOT 147456      // 128*128*9 anchors
#define HW    16384
#define GW    128
#define CIN   512
#define KTOT  4608        // 512*9
#define K2    9216        // 2*KTOT storage (hi, lo)
#define KSPLIT 12
#define KQ    1152        // logical K3 / KSPLIT  (13824/12)
#define BK    64
#define NCH   18          // KQ/BK
#define NCOL  1280
#define NU2   1152        // max unique columns padded to 128 (9 tiles)
#define NBLK  576
#define STEP  (2048.0f/127.0f)
#define ASTRIDE 72        // smem row stride in halves (64 + 8 pad)
#define STG   (256 * ASTRIDE)          // halves per stage (128 A rows + 128 B rows)
#define FST   132         // epilogue staging stride in floats (128 + 4)
#define WBLK  9216        // wconv blocks: CIN*KTOT/256
#define WREG  4608        // anchors per warp in selection (A_TOT/32)
#define WROWS 144

__constant__ float d_whw[9] = {128.0f, 181.01933598375618f, 90.50966799187809f,
                               256.0f, 362.03867196751236f, 181.01933598375618f,
                               512.0f, 724.0773439350247f, 362.03867196751236f};
__constant__ float d_whh[9] = {128.0f, 90.50966799187809f, 181.01933598375618f,
                               256.0f, 181.01933598375618f, 362.03867196751236f,
                               512.0f, 362.03867196751236f, 724.0773439350247f};

// ---------------- static device scratch ----------------
__device__ float d_maxIou[A_TOT];
__device__ int   d_tgtIdx[A_TOT];
__device__ int   d_posIdx[128];
__device__ int   d_posValid[128];
__device__ int   d_negValid[256];
__device__ int   d_nPos;
__device__ int   d_Upad;              // padded to 128
__device__ int   d_doneCnt;           // coldot last-block counter (reset in selection)
__device__ int   d_colPos[NCOL];
__device__ int   d_colMeta[NCOL];
__device__ int   d_uniqPos[NU2];
__device__ __align__(16) __nv_bfloat16 d_Wc[(size_t)CIN * K2];   // [m][hi(4608), lo(4608)]
__device__ __align__(16) __nv_bfloat16 d_Bc[(size_t)NU2 * K2];   // [u][hi(4608), lo(4608)]
__device__ float d_hp[KSPLIT * NU2 * CIN];                        // partials [ks][u][m]
__device__ float d_val[NCOL];

__device__ __forceinline__ uint32_t smem_u32(const void* p) {
    uint32_t a;
    asm("{ .reg .u64 t; cvta.to.shared.u64 t, %1; cvt.u32.u64 %0, t; }" : "=r"(a) : "l"(p));
    return a;
}

// ---------------- phase A: IoU matching (division-free) + fused wconv ----------------
__global__ void iou_wconv_kernel(const float* __restrict__ target,
                                 const float* __restrict__ W) {
    if (blockIdx.x < NBLK) {
        __shared__ float4 tg[64];
        int t = threadIdx.x;
        if (t < 64) tg[t] = ((const float4*)target)[t];
        __syncthreads();
        int a = blockIdx.x * 256 + t;
        int k = a % 9;
        int q = a / 9;
        int wq = q & 127;
        int hq = q >> 7;
        float x1 = hq * STEP;
        float y1 = wq * STEP;
        float x2 = x1 + d_whw[k];
        float y2 = y1 + d_whh[k];
        float areaA = (x2 - x1) * (y2 - y1);

        // running max of inter/denom via cross-multiplication (denoms > 0);
        // strict > keeps FIRST index on ties == jnp.argmax.
        float bestN = -1.0f, bestD = 1.0f;
        int bi = 0;
        #pragma unroll 4
        for (int i = 0; i < 64; i++) {
            float4 b = tg[i];
            float lx = fmaxf(b.x, x1), ly = fmaxf(b.y, y1);
            float rx = fminf(b.z, x2), ry = fminf(b.w, y2);
            float iw = fmaxf(rx - lx, 0.0f), ih = fmaxf(ry - ly, 0.0f);
            float inter = iw * ih;
            float at = (b.z - b.x) * (b.w - b.y);
            float denom = at + areaA - inter;
            if (inter * bestD > bestN * denom) { bestN = inter; bestD = denom; bi = i; }
        }
        d_maxIou[a] = bestN / bestD;
        d_tgtIdx[a] = bi;
    } else {
        int idx = (blockIdx.x - NBLK) * 256 + threadIdx.x;   // CIN*KTOT
        int m = idx / KTOT;
        int k = idx - m * KTOT;
        float v = W[idx];
        __nv_bfloat16 hi = __float2bfloat16(v);
        __nv_bfloat16 lo = __float2bfloat16(v - __bfloat162float(hi));
        __nv_bfloat16* o = d_Wc + (size_t)m * K2;
        o[k] = hi; o[KTOT + k] = lo;
    }
}

// ---------------- fallback sort (1024 threads) ----------------
__device__ __forceinline__ void bitonic2048(unsigned long long* s) {
    int t = threadIdx.x;
    for (int k = 2; k <= 2048; k <<= 1) {
        for (int j = k >> 1; j > 0; j >>= 1) {
            __syncthreads();
            #pragma unroll
            for (int base = 0; base < 2048; base += 1024) {
                int i = base + t;
                int ixj = i ^ j;
                if (ixj > i) {
                    unsigned long long va = s[i], vb = s[ixj];
                    bool sw = ((i & k) == 0) ? (va < vb) : (va > vb);
                    if (sw) { s[i] = vb; s[ixj] = va; }
                }
            }
        }
    }
    __syncthreads();
}

// ---------------- phase B: warp-parallel two-pass selection + column tables ----------------
__global__ void selection_kernel() {   // 1 block x 1024
    __shared__ unsigned long long pKeys[2048];
    __shared__ int zIdx[256];
    __shared__ int warpZ[32], warpP[32];
    __shared__ int zExS[32], pExS[32];
    __shared__ int pTotS;
    int t = threadIdx.x, lane = t & 31, w = t >> 5;
    unsigned lmLT = (1u << lane) - 1u;
    int wbase = w * WREG;
    if (t == 0) d_doneCnt = 0;     // reset last-block counter every replay

    // pass 1: per-warp class counts
    int nzW = 0, npW = 0;
    #pragma unroll 4
    for (int i = 0; i < WROWS; i++) {
        float v = d_maxIou[wbase + i * 32 + lane];
        bool z = (v < 0.3f) && ((1.0f - v) == 1.0f);   // exact ref tie-class
        bool p = (v > 0.7f);
        nzW += __popc(__ballot_sync(0xFFFFFFFFu, z));
        npW += __popc(__ballot_sync(0xFFFFFFFFu, p));
    }
    if (lane == 0) { warpZ[w] = nzW; warpP[w] = npW; }
    __syncthreads();
    if (w == 0) {
        int vz = warpZ[lane], vp = warpP[lane];
        int sz = vz, sp = vp;
        #pragma unroll
        for (int o = 1; o < 32; o <<= 1) {
            int xz = __shfl_up_sync(0xFFFFFFFFu, sz, o);
            int xp = __shfl_up_sync(0xFFFFFFFFu, sp, o);
            if (lane >= o) { sz += xz; sp += xp; }
        }
        zExS[lane] = sz - vz;
        pExS[lane] = sp - vp;
        if (lane == 31) pTotS = sp;
    }
    __syncthreads();

    // pass 2: replay with running bases; exact index-order ranks
    {
        int zr = zExS[w], pr = pExS[w];
        if (zr < 256 || pr < 2048) {
            for (int i = 0; i < WROWS; i++) {
                int a = wbase + i * 32 + lane;
                float v = d_maxIou[a];
                bool z = (v < 0.3f) && ((1.0f - v) == 1.0f);
                bool p = (v > 0.7f);
                unsigned bz = __ballot_sync(0xFFFFFFFFu, z);
                unsigned bp = __ballot_sync(0xFFFFFFFFu, p);
                if (z) {
                    int r = zr + __popc(bz & lmLT);
                    if (r < 256) zIdx[r] = a;
                }
                if (p) {
                    int r = pr + __popc(bp & lmLT);
                    if (r < 2048)
                        pKeys[r] = (((unsigned long long)__float_as_uint(v) << 32) |
                                    (0xFFFFFFFFu - (unsigned)a));
                }
                zr += __popc(bz);
                pr += __popc(bp);
                if (zr >= 256 && pr >= 2048) break;
            }
        }
    }
    __syncthreads();

    int cnt = pTotS;
    int npos = cnt < 128 ? cnt : 128;
    int K = 256 - npos;
    if (t == 0) {
        d_nPos = npos;
        int U = 513 + 4 * npos;
        d_Upad = (U + 127) & ~127;   // pad to 128 (GEMM N-tile)
    }
    if (cnt > 128) {
        int stored = cnt < 2048 ? cnt : 2048;
        for (int i = t; i < 2048; i += 1024)
            if (i >= stored) pKeys[i] = 0ULL;
        __syncthreads();
        bitonic2048(pKeys);
    }
    __syncthreads();
    if (t < 128) {
        int valid = (t < npos);
        d_posValid[t] = valid;
        if (valid) {
            int p = (int)(0xFFFFFFFFu - (unsigned)(pKeys[t] & 0xFFFFFFFFULL));
            d_posIdx[t] = p;
            int sb = (4 * p) & 16383;
            int ssc = (2 * p) & 16383;
            int cb = p >> 12;
            int cs = 36 + (p >> 13);
            #pragma unroll
            for (int e = 0; e < 4; e++) {
                d_colPos[4 * t + e] = sb + e;
                d_colMeta[4 * t + e] = cb;
            }
            #pragma unroll
            for (int e = 0; e < 2; e++) {
                d_colPos[512 + 2 * t + e] = ssc + e;
                d_colMeta[512 + 2 * t + e] = cs;
            }
        }
    }
    if (t < 256) {
        d_negValid[t] = (t < K);
        if (t < K) {
            int a = zIdx[t];
            int ss = (2 * a) & 16383;
            int cs = 36 + (a >> 13);
            d_colPos[768 + 2 * t] = ss;         d_colMeta[768 + 2 * t] = cs;
            d_colPos[768 + 2 * t + 1] = ss + 1; d_colMeta[768 + 2 * t + 1] = cs;
        }
    }
    __syncthreads();
    for (int u = t; u < NU2; u += 1024) {
        int pos = 0;
        if (u >= 1) {
            int v = u - 1;
            if (v < 4 * npos)              pos = d_colPos[v];
            else if (v < 6 * npos)         pos = d_colPos[512 + (v - 4 * npos)];
            else if (v < 6 * npos + 2 * K) pos = d_colPos[768 + (v - 6 * npos)];
        }
        d_uniqPos[u] = pos;
    }
}

// ---------------- gather: one thread per (u, ci, ky) reads a 3-wide patch row ----------------
// grid = NU2*512*3/256 = 6912 blocks
__global__ void gather_kernel(const float* __restrict__ x) {
    int idx = blockIdx.x * 256 + threadIdx.x;
    int u = idx / 1536;
    if (u >= d_Upad) return;
    int rem = idx - u * 1536;
    int ci = rem / 3;
    int ky = rem - ci * 3;
    int s = d_uniqPos[u];
    int y = (s >> 7) + ky - 1;
    int xc = s & 127;
    float v0 = 0.0f, v1 = 0.0f, v2 = 0.0f;
    if ((unsigned)y < 128u) {
        const float* rowp = x + ci * HW + y * GW;
        if (xc >= 1)   v0 = rowp[xc - 1];
        v1 = rowp[xc];
        if (xc <= 126) v2 = rowp[xc + 1];
    }
    __nv_bfloat16 h0 = __float2bfloat16(v0);
    __nv_bfloat16 h1 = __float2bfloat16(v1);
    __nv_bfloat16 h2 = __float2bfloat16(v2);
    __nv_bfloat16 l0 = __float2bfloat16(v0 - __bfloat162float(h0));
    __nv_bfloat16 l1 = __float2bfloat16(v1 - __bfloat162float(h1));
    __nv_bfloat16 l2 = __float2bfloat16(v2 - __bfloat162float(h2));
    int k = ci * 9 + ky * 3;
    __nv_bfloat16* o = d_Bc + (size_t)u * K2 + k;
    o[0] = h0; o[1] = h1; o[2] = h2;
    o[KTOT] = l0; o[KTOT + 1] = l1; o[KTOT + 2] = l2;
}

// ---------------- HMMA GEMM, cp.async 3-stage (1 sync/chunk), CTA 128x128 ----------------
// Logical K' = 13824 as 3 terms [WhiBhi, WhiBlo, WloBhi] over dedup [hi,lo] storage.
// grid (9, 4, KSPLIT=12), 256 threads (8 warps: 4M x 2N). Staged smem epilogue.
__global__ void __launch_bounds__(256, 2) gemm_hmma(void) {
    int n0 = blockIdx.x * 128;
    if (n0 >= d_Upad) return;                  // dedup early-exit
    int m0 = blockIdx.y * 128;
    int ks = blockIdx.z;
    int kq0 = ks * KQ;
    int aOff = kq0 - ((ks >= 4) ? KTOT : 0);   // Whi,Whi,Wlo
    int bOff = (ks >= 8) ? (kq0 - 2 * KTOT) : kq0;  // Bhi,Blo,Bhi

    extern __shared__ char smraw[];
    __nv_bfloat16* sm = (__nv_bfloat16*)smraw;
    uint32_t smBase = smem_u32(sm);

    int t = threadIdx.x;
    int wid = t >> 5, lane = t & 31;
    int wm = wid & 3, wn = wid >> 2;

    float acc[2][8][4];
    #pragma unroll
    for (int i = 0; i < 2; i++)
        #pragma unroll
        for (int j = 0; j < 8; j++)
            #pragma unroll
            for (int e = 0; e < 4; e++) acc[i][j][e] = 0.0f;

    int row = t >> 3, c16 = t & 7;
    const __nv_bfloat16* aG0 = d_Wc + (size_t)(m0 + row) * K2 + aOff + c16 * 8;
    const __nv_bfloat16* bG0 = d_Bc + (size_t)(n0 + row) * K2 + bOff + c16 * 8;
    uint32_t aS0 = smBase + 2 * (uint32_t)(row * ASTRIDE + c16 * 8);
    uint32_t bS0 = smBase + 2 * (uint32_t)(128 * ASTRIDE + row * ASTRIDE + c16 * 8);

    #define ISSUE(ch) do {                                                     \
        uint32_t so = 2u * (uint32_t)(((ch) % 3) * STG);                       \
        int ko = (ch) * BK;                                                    \
        _Pragma("unroll")                                                      \
        for (int i = 0; i < 4; i++)                                            \
            asm volatile("cp.async.cg.shared.global [%0], [%1], 16;"           \
                :: "r"(aS0 + so + 2u * (uint32_t)(i * 32 * ASTRIDE)),          \
                   "l"(aG0 + (size_t)i * 32 * K2 + ko) : "memory");            \
        _Pragma("unroll")                                                      \
        for (int i = 0; i < 4; i++)                                            \
            asm volatile("cp.async.cg.shared.global [%0], [%1], 16;"           \
                :: "r"(bS0 + so + 2u * (uint32_t)(i * 32 * ASTRIDE)),          \
                   "l"(bG0 + (size_t)i * 32 * K2 + ko) : "memory");            \
        asm volatile("cp.async.commit_group;" ::: "memory");                   \
    } while (0)

    ISSUE(0);
    ISSUE(1);

    for (int ch = 0; ch < NCH; ch++) {
        if (ch + 1 < NCH) asm volatile("cp.async.wait_group 1;" ::: "memory");
        else              asm volatile("cp.async.wait_group 0;" ::: "memory");
        __syncthreads();   // single barrier: data-ready + transitive buffer-reuse safety
        if (ch + 2 < NCH) ISSUE(ch + 2);

        uint32_t so = 2u * (uint32_t)((ch % 3) * STG);
        #pragma unroll
        for (int s = 0; s < 4; s++) {          // 4 k16 steps per BK=64
            int koff = s * 16;
            uint32_t a[2][4], b[4][4];
            #pragma unroll
            for (int tm = 0; tm < 2; tm++) {
                uint32_t addr = smBase + so + 2 * (uint32_t)(
                    (wm * 32 + tm * 16 + (lane & 15)) * ASTRIDE + koff + ((lane >> 4) << 3));
                asm volatile("ldmatrix.sync.aligned.m8n8.x4.shared.b16 {%0,%1,%2,%3}, [%4];"
                    : "=r"(a[tm][0]), "=r"(a[tm][1]), "=r"(a[tm][2]), "=r"(a[tm][3]) : "r"(addr));
            }
            #pragma unroll
            for (int p = 0; p < 4; p++) {
                int g = lane >> 3;
                int brow = wn * 64 + p * 16 + ((g >> 1) << 3) + (lane & 7);
                int kadd = (g & 1) << 3;
                uint32_t addr = smBase + so + 2 * (uint32_t)(
                    128 * ASTRIDE + brow * ASTRIDE + koff + kadd);
                asm volatile("ldmatrix.sync.aligned.m8n8.x4.shared.b16 {%0,%1,%2,%3}, [%4];"
                    : "=r"(b[p][0]), "=r"(b[p][1]), "=r"(b[p][2]), "=r"(b[p][3]) : "r"(addr));
            }
            #pragma unroll
            for (int tm = 0; tm < 2; tm++)
                #pragma unroll
                for (int tn = 0; tn < 8; tn++) {
                    int p = tn >> 1, h = (tn & 1) << 1;
                    asm volatile(
                        "mma.sync.aligned.m16n8k16.row.col.f32.bf16.bf16.f32 "
                        "{%0,%1,%2,%3}, {%4,%5,%6,%7}, {%8,%9}, {%0,%1,%2,%3};"
                        : "+f"(acc[tm][tn][0]), "+f"(acc[tm][tn][1]),
                          "+f"(acc[tm][tn][2]), "+f"(acc[tm][tn][3])
                        : "r"(a[tm][0]), "r"(a[tm][1]), "r"(a[tm][2]), "r"(a[tm][3]),
                          "r"(b[p][h]), "r"(b[p][h + 1]));
                }
        }
    }
    __syncthreads();   // all warps done reading smem before epilogue reuse

    // ---- staged epilogue: acc -> smem [u][m] (stride FST) -> coalesced gmem ----
    float* smF = (float*)smraw;
    int g = lane >> 2, tq = lane & 3;
    #pragma unroll
    for (int tm = 0; tm < 2; tm++) {
        int rm = wm * 32 + tm * 16 + g;
        #pragma unroll
        for (int tn = 0; tn < 8; tn++) {
            int cn = wn * 64 + tn * 8 + tq * 2;
            smF[cn * FST + rm]           = acc[tm][tn][0];
            smF[(cn + 1) * FST + rm]     = acc[tm][tn][1];
            smF[cn * FST + rm + 8]       = acc[tm][tn][2];
            smF[(cn + 1) * FST + rm + 8] = acc[tm][tn][3];
        }
    }
    __syncthreads();
    float* hpBase = d_hp + (size_t)(ks * NU2 + n0) * CIN + m0;
    for (int i = t; i < 128 * 32; i += 256) {
        int u = i >> 5, m4 = (i & 31) << 2;
        float4 v = *(float4*)&smF[u * FST + m4];
        *(float4*)(hpBase + (size_t)u * CIN + m4) = v;
    }
}

// ---------------- coldot + fused loss (last-block pattern) ----------------
__global__ void coldot_loss_kernel(const float* __restrict__ bw, const float* __restrict__ bb,
                                   const float* __restrict__ sw, const float* __restrict__ sb,
                                   const float* __restrict__ conv_b,
                                   const float* __restrict__ target,
                                   float* __restrict__ out) {
    __shared__ int isLast;
    __shared__ float rce[256], rsl[256], rvc[256];
    int tid = threadIdx.x;
    int col = blockIdx.x * 8 + (tid >> 5);
    int lane = tid & 31;
    int npos = d_nPos;
    int u;
    if (col < 512)      { int t = col >> 2;         u = (t < npos) ? 1 + col : 0; }
    else if (col < 768) { int t = (col - 512) >> 1; u = (t < npos) ? 1 + 4 * npos + (col - 512) : 0; }
    else                { int g = (col - 768) >> 1; u = (g < 256 - npos) ? 1 + 6 * npos + (col - 768) : 0; }
    if (u != 0) {
        int meta = d_colMeta[col];
        const float* w;
        float b;
        if (meta < 36) { w = bw + meta * 512; b = bb[meta]; }
        else           { w = sw + (meta - 36) * 512; b = sb[meta - 36]; }
        const float4* wv = (const float4*)w;
        const float4* bias4 = (const float4*)conv_b;
        float s = 0.0f;
        for (int i = lane; i < 128; i += 32) {
            float4 a = bias4[i];
            #pragma unroll
            for (int ks = 0; ks < KSPLIT; ks++) {
                const float4* hp4 = (const float4*)(d_hp + (size_t)(ks * NU2 + u) * CIN);
                float4 hv = hp4[i];
                a.x += hv.x; a.y += hv.y; a.z += hv.z; a.w += hv.w;
            }
            a.x = fmaxf(a.x, 0.0f); a.y = fmaxf(a.y, 0.0f);
            a.z = fmaxf(a.z, 0.0f); a.w = fmaxf(a.w, 0.0f);
            float4 ww = wv[i];
            s += a.x * ww.x + a.y * ww.y + a.z * ww.z + a.w * ww.w;
        }
        #pragma unroll
        for (int o = 16; o > 0; o >>= 1) s += __shfl_xor_sync(0xFFFFFFFFu, s, o);
        if (lane == 0) d_val[col] = fmaxf(s + b, 0.0f);
    }

    // last block computes the loss
    __threadfence();
    __syncthreads();
    if (tid == 0) isLast = (atomicAdd(&d_doneCnt, 1) == (int)gridDim.x - 1);
    __syncthreads();
    if (!isLast) return;

    int t = tid;
    float ce = 0.0f, sl = 0.0f, vc = 0.0f;
    if (t < 128 && d_posValid[t]) {
        float s0 = d_val[512 + 2 * t], s1 = d_val[512 + 2 * t + 1];
        float m = fmaxf(s0, s1);
        float lse = m + logf(expf(s0 - m) + expf(s1 - m));
        ce += lse - s0;
        vc += 1.0f;
        int p = d_posIdx[t];
        int k = p % 9;
        int q = p / 9;
        int wq = q & 127;
        int hq = q >> 7;
        float ax1 = hq * STEP, ay1 = wq * STEP;
        float aw = d_whw[k], ah = d_whh[k];
        float acx = ax1 + aw * 0.5f, acy = ay1 + ah * 0.5f;
        float4 tb = ((const float4*)target)[d_tgtIdx[p]];
        float bw_ = tb.z - tb.x, bh_ = tb.w - tb.y;
        float bcx = tb.x + bw_ * 0.5f, bcy = tb.y + bh_ * 0.5f;
        float tr[4] = {(bcx - acx) / aw, (bcy - acy) / ah,
                       logf(bw_ / aw), logf(bh_ / ah)};
        #pragma unroll
        for (int e = 0; e < 4; e++) {
            float dd = d_val[4 * t + e] - tr[e];
            float ad = fabsf(dd);
            sl += (ad < 1.0f) ? 0.5f * dd * dd : (ad - 0.5f);
        }
    }
    if (t < 256 && d_negValid[t]) {
        float s0 = d_val[768 + 2 * t], s1 = d_val[768 + 2 * t + 1];
        float m = fmaxf(s0, s1);
        float lse = m + logf(expf(s0 - m) + expf(s1 - m));
        ce += lse - s1;
        vc += 1.0f;
    }
    rce[t] = ce; rsl[t] = sl; rvc[t] = vc;
    __syncthreads();
    for (int s2 = 128; s2 > 0; s2 >>= 1) {
        if (t < s2) { rce[t] += rce[t + s2]; rsl[t] += rsl[t + s2]; rvc[t] += rvc[t + s2]; }
        __syncthreads();
    }
    if (t == 0) {
        float np = (float)d_nPos;
        float score_loss = rce[0] / fmaxf(rvc[0], 1.0f);
        float reg_loss = rsl[0] / fmaxf(np * 4.0f, 1.0f);
        out[0] = score_loss + 10.0f * reg_loss;
    }
}

// ---------------- launch ----------------
extern "C" void kernel_launch(void* const* d_in, const int* in_sizes, int n_in,
                              void* d_out, int out_size) {
    const float* x       = (const float*)d_in[0];
    const float* target  = (const float*)d_in[1];
    const float* conv_w  = (const float*)d_in[2];
    const float* conv_b  = (const float*)d_in[3];
    const float* bbox_w  = (const float*)d_in[4];
    const float* bbox_b  = (const float*)d_in[5];
    const float* score_w = (const float*)d_in[6];
    const float* score_b = (const float*)d_in[7];
    float* out = (float*)d_out;

    // smem: 3 stages x 256*72 halves * 2B = 110592 B (epilogue reuses 67.6 KB of it)
    const int DSMEM = 3 * STG * 2;
    cudaFuncSetAttribute(gemm_hmma, cudaFuncAttributeMaxDynamicSharedMemorySize, DSMEM);

    iou_wconv_kernel<<<NBLK + WBLK, 256>>>(target, conv_w);
    selection_kernel<<<1, 1024>>>();
    gather_kernel<<<(NU2 * 1536) / 256, 256>>>(x);
    gemm_hmma<<<dim3(NU2 / 128, CIN / 128, KSPLIT), 256, DSMEM>>>();
    coldot_loss_kernel<<<NCOL / 8, 256>>>(bbox_w, bbox_b, score_w, score_b,
                                          conv_b, target, out);
}

// round 17
// speedup vs baseline: 1.0250x; 1.0250x over previous
#include <cuda_runtime.h>
#include <cuda_bf16.h>
#include <math.h>
#include <stdint.h>

#define A_TOT 147456      // 128*128*9 anchors
#define HW    16384
#define GW    128
#define CIN   512
#define KTOT  4608        // 512*9
#define K2    9216        // 2*KTOT storage (hi, lo)
#define KSPLIT 12
#define KQ    1152        // logical K3 / KSPLIT  (13824/12)
#define BK    64
#define NCH   18          // KQ/BK
#define NCOL  1280
#define NU2   1152        // max unique columns padded to 128 (9 tiles)
#define IBLK  576         // iou blocks: 9 k * 64 hq-pairs
#define STEP  (2048.0f/127.0f)
#define ASTRIDE 72        // smem row stride in halves (64 + 8 pad)
#define STG   (256 * ASTRIDE)          // halves per stage (128 A rows + 128 B rows)
#define FST   132         // epilogue staging stride in floats (128 + 4)
#define WBLK  9216        // wconv blocks: CIN*KTOT/256
#define WREG  4608        // anchors per warp in selection (A_TOT/32)
#define WROWS 144

__constant__ float d_whw[9] = {128.0f, 181.01933598375618f, 90.50966799187809f,
                               256.0f, 362.03867196751236f, 181.01933598375618f,
                               512.0f, 724.0773439350247f, 362.03867196751236f};
__constant__ float d_whh[9] = {128.0f, 90.50966799187809f, 181.01933598375618f,
                               256.0f, 181.01933598375618f, 362.03867196751236f,
                               512.0f, 362.03867196751236f, 724.0773439350247f};

// ---------------- static device scratch ----------------
__device__ float d_maxIou[A_TOT];
__device__ int   d_tgtIdx[A_TOT];
__device__ int   d_posIdx[128];
__device__ int   d_posValid[128];
__device__ int   d_negValid[256];
__device__ int   d_nPos;
__device__ int   d_Upad;              // padded to 128
__device__ int   d_doneCnt;           // coldot last-block counter (reset in selection)
__device__ int   d_colPos[NCOL];
__device__ int   d_colMeta[NCOL];
__device__ int   d_uniqPos[NU2];
__device__ __align__(16) __nv_bfloat16 d_Wc[(size_t)CIN * K2];   // [m][hi(4608), lo(4608)]
__device__ __align__(16) __nv_bfloat16 d_Bc[(size_t)NU2 * K2];   // [u][hi(4608), lo(4608)]
__device__ float d_hp[KSPLIT * NU2 * CIN];                        // partials [ks][u][m]
__device__ float d_val[NCOL];

__device__ __forceinline__ uint32_t smem_u32(const void* p) {
    uint32_t a;
    asm("{ .reg .u64 t; cvta.to.shared.u64 t, %1; cvt.u32.u64 %0, t; }" : "=r"(a) : "l"(p));
    return a;
}

// ---------------- phase A: IoU (x-slab pruned, separable) + fused wconv ----------------
// iou block: fixed k, two hq values (halves of the 256-thread block). Per block the
// anchor x-interval is FIXED, so each target's x-overlap iw is computed ONCE; targets
// with iw<=0 have inter==0 for every anchor in the block (iou exactly 0) and are pruned.
// Semantics proof: pruned targets can never win the cross-mul max unless max==0, in
// which case the stored value is 0.0f either way; tgtIdx is only consumed for positive
// anchors (iou>0.7), whose argmax target has iou>0.7 and is never pruned.
__global__ void iou_wconv_kernel(const float* __restrict__ target,
                                 const float* __restrict__ W) {
    if (blockIdx.x < IBLK) {
        __shared__ float4 kept[2][64];   // (iw, ty1, ty2, at+areaA)
        __shared__ int    kidx[2][64];
        __shared__ int    kcnt[2];
        int t = threadIdx.x;
        int k  = blockIdx.x / 64;
        int hp = (blockIdx.x - k * 64) * 2;
        int half = t >> 7;               // 0 or 1
        int wq = t & 127;
        int hq = hp + half;
        float whwk = d_whw[k], whhk = d_whh[k];
        float areaA = whwk * whhk;
        int wid = t >> 5, lane = t & 31;

        // setup: warps 0 and 4 build the kept lists for their half
        if (wid == 0 || wid == 4) {
            int h = wid >> 2;
            float x1 = (hp + h) * STEP;
            float x2 = x1 + whwk;
            int base = 0;
            #pragma unroll
            for (int ho = 0; ho < 2; ho++) {
                int i = ho * 32 + lane;
                float4 tb = ((const float4*)target)[i];
                float iw = fminf(tb.z, x2) - fmaxf(tb.x, x1);
                bool keep = iw > 0.0f;
                unsigned m = __ballot_sync(0xFFFFFFFFu, keep);
                if (keep) {
                    int r = base + __popc(m & ((1u << lane) - 1));
                    float at = (tb.z - tb.x) * (tb.w - tb.y);
                    kept[h][r] = make_float4(iw, tb.y, tb.w, at + areaA);
                    kidx[h][r] = i;
                }
                base += __popc(m);
            }
            if (lane == 0) kcnt[h] = base;
        }
        __syncthreads();

        int kc = kcnt[half];
        float y1 = wq * STEP;
        float y2 = y1 + whhk;
        float bestN = -1.0f, bestD = 1.0f;
        int bi = 0;
        for (int r = 0; r < kc; r++) {
            float4 kt = kept[half][r];
            float ly = fmaxf(kt.y, y1), ry = fminf(kt.z, y2);
            float ih = fmaxf(ry - ly, 0.0f);
            float inter = kt.x * ih;               // == ref's iw*ih (iw>0 here)
            float denom = kt.w - inter;            // == (at+areaA) - inter, same fp order
            if (inter * bestD > bestN * denom) {   // strict > keeps first index on ties
                bestN = inter; bestD = denom; bi = kidx[half][r];
            }
        }
        int a = ((hq << 7) | wq) * 9 + k;
        d_maxIou[a] = (kc > 0) ? (bestN / bestD) : 0.0f;
        d_tgtIdx[a] = (kc > 0) ? bi : 0;
    } else {
        int idx = (blockIdx.x - IBLK) * 256 + threadIdx.x;   // CIN*KTOT
        int m = idx / KTOT;
        int k = idx - m * KTOT;
        float v = W[idx];
        __nv_bfloat16 hi = __float2bfloat16(v);
        __nv_bfloat16 lo = __float2bfloat16(v - __bfloat162float(hi));
        __nv_bfloat16* o = d_Wc + (size_t)m * K2;
        o[k] = hi; o[KTOT + k] = lo;
    }
}

// ---------------- fallback sort (1024 threads) ----------------
__device__ __forceinline__ void bitonic2048(unsigned long long* s) {
    int t = threadIdx.x;
    for (int k = 2; k <= 2048; k <<= 1) {
        for (int j = k >> 1; j > 0; j >>= 1) {
            __syncthreads();
            #pragma unroll
            for (int base = 0; base < 2048; base += 1024) {
                int i = base + t;
                int ixj = i ^ j;
                if (ixj > i) {
                    unsigned long long va = s[i], vb = s[ixj];
                    bool sw = ((i & k) == 0) ? (va < vb) : (va > vb);
                    if (sw) { s[i] = vb; s[ixj] = va; }
                }
            }
        }
    }
    __syncthreads();
}

// ---------------- phase B: warp-parallel two-pass selection + column tables ----------------
__global__ void selection_kernel() {   // 1 block x 1024
    __shared__ unsigned long long pKeys[2048];
    __shared__ int zIdx[256];
    __shared__ int warpZ[32], warpP[32];
    __shared__ int zExS[32], pExS[32];
    __shared__ int pTotS;
    int t = threadIdx.x, lane = t & 31, w = t >> 5;
    unsigned lmLT = (1u << lane) - 1u;
    int wbase = w * WREG;
    if (t == 0) d_doneCnt = 0;     // reset last-block counter every replay

    // pass 1: per-warp class counts
    int nzW = 0, npW = 0;
    #pragma unroll 4
    for (int i = 0; i < WROWS; i++) {
        float v = d_maxIou[wbase + i * 32 + lane];
        bool z = (v < 0.3f) && ((1.0f - v) == 1.0f);   // exact ref tie-class
        bool p = (v > 0.7f);
        nzW += __popc(__ballot_sync(0xFFFFFFFFu, z));
        npW += __popc(__ballot_sync(0xFFFFFFFFu, p));
    }
    if (lane == 0) { warpZ[w] = nzW; warpP[w] = npW; }
    __syncthreads();
    if (w == 0) {
        int vz = warpZ[lane], vp = warpP[lane];
        int sz = vz, sp = vp;
        #pragma unroll
        for (int o = 1; o < 32; o <<= 1) {
            int xz = __shfl_up_sync(0xFFFFFFFFu, sz, o);
            int xp = __shfl_up_sync(0xFFFFFFFFu, sp, o);
            if (lane >= o) { sz += xz; sp += xp; }
        }
        zExS[lane] = sz - vz;
        pExS[lane] = sp - vp;
        if (lane == 31) pTotS = sp;
    }
    __syncthreads();

    // pass 2: replay with running bases; exact index-order ranks
    {
        int zr = zExS[w], pr = pExS[w];
        if (zr < 256 || pr < 2048) {
            for (int i = 0; i < WROWS; i++) {
                int a = wbase + i * 32 + lane;
                float v = d_maxIou[a];
                bool z = (v < 0.3f) && ((1.0f - v) == 1.0f);
                bool p = (v > 0.7f);
                unsigned bz = __ballot_sync(0xFFFFFFFFu, z);
                unsigned bp = __ballot_sync(0xFFFFFFFFu, p);
                if (z) {
                    int r = zr + __popc(bz & lmLT);
                    if (r < 256) zIdx[r] = a;
                }
                if (p) {
                    int r = pr + __popc(bp & lmLT);
                    if (r < 2048)
                        pKeys[r] = (((unsigned long long)__float_as_uint(v) << 32) |
                                    (0xFFFFFFFFu - (unsigned)a));
                }
                zr += __popc(bz);
                pr += __popc(bp);
                if (zr >= 256 && pr >= 2048) break;
            }
        }
    }
    __syncthreads();

    int cnt = pTotS;
    int npos = cnt < 128 ? cnt : 128;
    int K = 256 - npos;
    if (t == 0) {
        d_nPos = npos;
        int U = 513 + 4 * npos;
        d_Upad = (U + 127) & ~127;   // pad to 128 (GEMM N-tile)
    }
    if (cnt > 128) {
        int stored = cnt < 2048 ? cnt : 2048;
        for (int i = t; i < 2048; i += 1024)
            if (i >= stored) pKeys[i] = 0ULL;
        __syncthreads();
        bitonic2048(pKeys);
    }
    __syncthreads();
    if (t < 128) {
        int valid = (t < npos);
        d_posValid[t] = valid;
        if (valid) {
            int p = (int)(0xFFFFFFFFu - (unsigned)(pKeys[t] & 0xFFFFFFFFULL));
            d_posIdx[t] = p;
            int sb = (4 * p) & 16383;
            int ssc = (2 * p) & 16383;
            int cb = p >> 12;
            int cs = 36 + (p >> 13);
            #pragma unroll
            for (int e = 0; e < 4; e++) {
                d_colPos[4 * t + e] = sb + e;
                d_colMeta[4 * t + e] = cb;
            }
            #pragma unroll
            for (int e = 0; e < 2; e++) {
                d_colPos[512 + 2 * t + e] = ssc + e;
                d_colMeta[512 + 2 * t + e] = cs;
            }
        }
    }
    if (t < 256) {
        d_negValid[t] = (t < K);
        if (t < K) {
            int a = zIdx[t];
            int ss = (2 * a) & 16383;
            int cs = 36 + (a >> 13);
            d_colPos[768 + 2 * t] = ss;         d_colMeta[768 + 2 * t] = cs;
            d_colPos[768 + 2 * t + 1] = ss + 1; d_colMeta[768 + 2 * t + 1] = cs;
        }
    }
    __syncthreads();
    for (int u = t; u < NU2; u += 1024) {
        int pos = 0;
        if (u >= 1) {
            int v = u - 1;
            if (v < 4 * npos)              pos = d_colPos[v];
            else if (v < 6 * npos)         pos = d_colPos[512 + (v - 4 * npos)];
            else if (v < 6 * npos + 2 * K) pos = d_colPos[768 + (v - 6 * npos)];
        }
        d_uniqPos[u] = pos;
    }
}

// ---------------- gather: one thread per (u, ci, ky) reads a 3-wide patch row ----------------
__global__ void gather_kernel(const float* __restrict__ x) {
    int idx = blockIdx.x * 256 + threadIdx.x;
    int u = idx / 1536;
    if (u >= d_Upad) return;
    int rem = idx - u * 1536;
    int ci = rem / 3;
    int ky = rem - ci * 3;
    int s = d_uniqPos[u];
    int y = (s >> 7) + ky - 1;
    int xc = s & 127;
    float v0 = 0.0f, v1 = 0.0f, v2 = 0.0f;
    if ((unsigned)y < 128u) {
        const float* rowp = x + ci * HW + y * GW;
        if (xc >= 1)   v0 = rowp[xc - 1];
        v1 = rowp[xc];
        if (xc <= 126) v2 = rowp[xc + 1];
    }
    __nv_bfloat16 h0 = __float2bfloat16(v0);
    __nv_bfloat16 h1 = __float2bfloat16(v1);
    __nv_bfloat16 h2 = __float2bfloat16(v2);
    __nv_bfloat16 l0 = __float2bfloat16(v0 - __bfloat162float(h0));
    __nv_bfloat16 l1 = __float2bfloat16(v1 - __bfloat162float(h1));
    __nv_bfloat16 l2 = __float2bfloat16(v2 - __bfloat162float(h2));
    int k = ci * 9 + ky * 3;
    __nv_bfloat16* o = d_Bc + (size_t)u * K2 + k;
    o[0] = h0; o[1] = h1; o[2] = h2;
    o[KTOT] = l0; o[KTOT + 1] = l1; o[KTOT + 2] = l2;
}

// ---------------- HMMA GEMM, cp.async 3-stage (1 sync/chunk), CTA 128x128 ----------------
__global__ void __launch_bounds__(256, 2) gemm_hmma(void) {
    int n0 = blockIdx.x * 128;
    if (n0 >= d_Upad) return;                  // dedup early-exit
    int m0 = blockIdx.y * 128;
    int ks = blockIdx.z;
    int kq0 = ks * KQ;
    int aOff = kq0 - ((ks >= 4) ? KTOT : 0);   // Whi,Whi,Wlo
    int bOff = (ks >= 8) ? (kq0 - 2 * KTOT) : kq0;  // Bhi,Blo,Bhi

    extern __shared__ char smraw[];
    __nv_bfloat16* sm = (__nv_bfloat16*)smraw;
    uint32_t smBase = smem_u32(sm);

    int t = threadIdx.x;
    int wid = t >> 5, lane = t & 31;
    int wm = wid & 3, wn = wid >> 2;

    float acc[2][8][4];
    #pragma unroll
    for (int i = 0; i < 2; i++)
        #pragma unroll
        for (int j = 0; j < 8; j++)
            #pragma unroll
            for (int e = 0; e < 4; e++) acc[i][j][e] = 0.0f;

    int row = t >> 3, c16 = t & 7;
    const __nv_bfloat16* aG0 = d_Wc + (size_t)(m0 + row) * K2 + aOff + c16 * 8;
    const __nv_bfloat16* bG0 = d_Bc + (size_t)(n0 + row) * K2 + bOff + c16 * 8;
    uint32_t aS0 = smBase + 2 * (uint32_t)(row * ASTRIDE + c16 * 8);
    uint32_t bS0 = smBase + 2 * (uint32_t)(128 * ASTRIDE + row * ASTRIDE + c16 * 8);

    #define ISSUE(ch) do {                                                     \
        uint32_t so = 2u * (uint32_t)(((ch) % 3) * STG);                       \
        int ko = (ch) * BK;                                                    \
        _Pragma("unroll")                                                      \
        for (int i = 0; i < 4; i++)                                            \
            asm volatile("cp.async.cg.shared.global [%0], [%1], 16;"           \
                :: "r"(aS0 + so + 2u * (uint32_t)(i * 32 * ASTRIDE)),          \
                   "l"(aG0 + (size_t)i * 32 * K2 + ko) : "memory");            \
        _Pragma("unroll")                                                      \
        for (int i = 0; i < 4; i++)                                            \
            asm volatile("cp.async.cg.shared.global [%0], [%1], 16;"           \
                :: "r"(bS0 + so + 2u * (uint32_t)(i * 32 * ASTRIDE)),          \
                   "l"(bG0 + (size_t)i * 32 * K2 + ko) : "memory");            \
        asm volatile("cp.async.commit_group;" ::: "memory");                   \
    } while (0)

    ISSUE(0);
    ISSUE(1);

    for (int ch = 0; ch < NCH; ch++) {
        if (ch + 1 < NCH) asm volatile("cp.async.wait_group 1;" ::: "memory");
        else              asm volatile("cp.async.wait_group 0;" ::: "memory");
        __syncthreads();   // single barrier: data-ready + transitive buffer-reuse safety
        if (ch + 2 < NCH) ISSUE(ch + 2);

        uint32_t so = 2u * (uint32_t)((ch % 3) * STG);
        #pragma unroll
        for (int s = 0; s < 4; s++) {          // 4 k16 steps per BK=64
            int koff = s * 16;
            uint32_t a[2][4], b[4][4];
            #pragma unroll
            for (int tm = 0; tm < 2; tm++) {
                uint32_t addr = smBase + so + 2 * (uint32_t)(
                    (wm * 32 + tm * 16 + (lane & 15)) * ASTRIDE + koff + ((lane >> 4) << 3));
                asm volatile("ldmatrix.sync.aligned.m8n8.x4.shared.b16 {%0,%1,%2,%3}, [%4];"
                    : "=r"(a[tm][0]), "=r"(a[tm][1]), "=r"(a[tm][2]), "=r"(a[tm][3]) : "r"(addr));
            }
            #pragma unroll
            for (int p = 0; p < 4; p++) {
                int g = lane >> 3;
                int brow = wn * 64 + p * 16 + ((g >> 1) << 3) + (lane & 7);
                int kadd = (g & 1) << 3;
                uint32_t addr = smBase + so + 2 * (uint32_t)(
                    128 * ASTRIDE + brow * ASTRIDE + koff + kadd);
                asm volatile("ldmatrix.sync.aligned.m8n8.x4.shared.b16 {%0,%1,%2,%3}, [%4];"
                    : "=r"(b[p][0]), "=r"(b[p][1]), "=r"(b[p][2]), "=r"(b[p][3]) : "r"(addr));
            }
            #pragma unroll
            for (int tm = 0; tm < 2; tm++)
                #pragma unroll
                for (int tn = 0; tn < 8; tn++) {
                    int p = tn >> 1, h = (tn & 1) << 1;
                    asm volatile(
                        "mma.sync.aligned.m16n8k16.row.col.f32.bf16.bf16.f32 "
                        "{%0,%1,%2,%3}, {%4,%5,%6,%7}, {%8,%9}, {%0,%1,%2,%3};"
                        : "+f"(acc[tm][tn][0]), "+f"(acc[tm][tn][1]),
                          "+f"(acc[tm][tn][2]), "+f"(acc[tm][tn][3])
                        : "r"(a[tm][0]), "r"(a[tm][1]), "r"(a[tm][2]), "r"(a[tm][3]),
                          "r"(b[p][h]), "r"(b[p][h + 1]));
                }
        }
    }
    __syncthreads();   // all warps done reading smem before epilogue reuse

    // ---- staged epilogue: acc -> smem [u][m] (stride FST) -> coalesced gmem ----
    float* smF = (float*)smraw;
    int g = lane >> 2, tq = lane & 3;
    #pragma unroll
    for (int tm = 0; tm < 2; tm++) {
        int rm = wm * 32 + tm * 16 + g;
        #pragma unroll
        for (int tn = 0; tn < 8; tn++) {
            int cn = wn * 64 + tn * 8 + tq * 2;
            smF[cn * FST + rm]           = acc[tm][tn][0];
            smF[(cn + 1) * FST + rm]     = acc[tm][tn][1];
            smF[cn * FST + rm + 8]       = acc[tm][tn][2];
            smF[(cn + 1) * FST + rm + 8] = acc[tm][tn][3];
        }
    }
    __syncthreads();
    float* hpBase = d_hp + (size_t)(ks * NU2 + n0) * CIN + m0;
    for (int i = t; i < 128 * 32; i += 256) {
        int u = i >> 5, m4 = (i & 31) << 2;
        float4 v = *(float4*)&smF[u * FST + m4];
        *(float4*)(hpBase + (size_t)u * CIN + m4) = v;
    }
}

// ---------------- coldot + fused loss (last-block pattern) ----------------
__global__ void coldot_loss_kernel(const float* __restrict__ bw, const float* __restrict__ bb,
                                   const float* __restrict__ sw, const float* __restrict__ sb,
                                   const float* __restrict__ conv_b,
                                   const float* __restrict__ target,
                                   float* __restrict__ out) {
    __shared__ int isLast;
    __shared__ float rce[256], rsl[256], rvc[256];
    int tid = threadIdx.x;
    int col = blockIdx.x * 8 + (tid >> 5);
    int lane = tid & 31;
    int npos = d_nPos;
    int u;
    if (col < 512)      { int t = col >> 2;         u = (t < npos) ? 1 + col : 0; }
    else if (col < 768) { int t = (col - 512) >> 1; u = (t < npos) ? 1 + 4 * npos + (col - 512) : 0; }
    else                { int g = (col - 768) >> 1; u = (g < 256 - npos) ? 1 + 6 * npos + (col - 768) : 0; }
    if (u != 0) {
        int meta = d_colMeta[col];
        const float* w;
        float b;
        if (meta < 36) { w = bw + meta * 512; b = bb[meta]; }
        else           { w = sw + (meta - 36) * 512; b = sb[meta - 36]; }
        const float4* wv = (const float4*)w;
        const float4* bias4 = (const float4*)conv_b;
        float s = 0.0f;
        for (int i = lane; i < 128; i += 32) {
            float4 a = bias4[i];
            #pragma unroll
            for (int ks = 0; ks < KSPLIT; ks++) {
                const float4* hp4 = (const float4*)(d_hp + (size_t)(ks * NU2 + u) * CIN);
                float4 hv = hp4[i];
                a.x += hv.x; a.y += hv.y; a.z += hv.z; a.w += hv.w;
            }
            a.x = fmaxf(a.x, 0.0f); a.y = fmaxf(a.y, 0.0f);
            a.z = fmaxf(a.z, 0.0f); a.w = fmaxf(a.w, 0.0f);
            float4 ww = wv[i];
            s += a.x * ww.x + a.y * ww.y + a.z * ww.z + a.w * ww.w;
        }
        #pragma unroll
        for (int o = 16; o > 0; o >>= 1) s += __shfl_xor_sync(0xFFFFFFFFu, s, o);
        if (lane == 0) d_val[col] = fmaxf(s + b, 0.0f);
    }

    // last block computes the loss
    __threadfence();
    __syncthreads();
    if (tid == 0) isLast = (atomicAdd(&d_doneCnt, 1) == (int)gridDim.x - 1);
    __syncthreads();
    if (!isLast) return;

    int t = tid;
    float ce = 0.0f, sl = 0.0f, vc = 0.0f;
    if (t < 128 && d_posValid[t]) {
        float s0 = d_val[512 + 2 * t], s1 = d_val[512 + 2 * t + 1];
        float m = fmaxf(s0, s1);
        float lse = m + logf(expf(s0 - m) + expf(s1 - m));
        ce += lse - s0;
        vc += 1.0f;
        int p = d_posIdx[t];
        int k = p % 9;
        int q = p / 9;
        int wq = q & 127;
        int hq = q >> 7;
        float ax1 = hq * STEP, ay1 = wq * STEP;
        float aw = d_whw[k], ah = d_whh[k];
        float acx = ax1 + aw * 0.5f, acy = ay1 + ah * 0.5f;
        float4 tb = ((const float4*)target)[d_tgtIdx[p]];
        float bw_ = tb.z - tb.x, bh_ = tb.w - tb.y;
        float bcx = tb.x + bw_ * 0.5f, bcy = tb.y + bh_ * 0.5f;
        float tr[4] = {(bcx - acx) / aw, (bcy - acy) / ah,
                       logf(bw_ / aw), logf(bh_ / ah)};
        #pragma unroll
        for (int e = 0; e < 4; e++) {
            float dd = d_val[4 * t + e] - tr[e];
            float ad = fabsf(dd);
            sl += (ad < 1.0f) ? 0.5f * dd * dd : (ad - 0.5f);
        }
    }
    if (t < 256 && d_negValid[t]) {
        float s0 = d_val[768 + 2 * t], s1 = d_val[768 + 2 * t + 1];
        float m = fmaxf(s0, s1);
        float lse = m + logf(expf(s0 - m) + expf(s1 - m));
        ce += lse - s1;
        vc += 1.0f;
    }
    rce[t] = ce; rsl[t] = sl; rvc[t] = vc;
    __syncthreads();
    for (int s2 = 128; s2 > 0; s2 >>= 1) {
        if (t < s2) { rce[t] += rce[t + s2]; rsl[t] += rsl[t + s2]; rvc[t] += rvc[t + s2]; }
        __syncthreads();
    }
    if (t == 0) {
        float np = (float)d_nPos;
        float score_loss = rce[0] / fmaxf(rvc[0], 1.0f);
        float reg_loss = rsl[0] / fmaxf(np * 4.0f, 1.0f);
        out[0] = score_loss + 10.0f * reg_loss;
    }
}

// ---------------- launch ----------------
extern "C" void kernel_launch(void* const* d_in, const int* in_sizes, int n_in,
                              void* d_out, int out_size) {
    const float* x       = (const float*)d_in[0];
    const float* target  = (const float*)d_in[1];
    const float* conv_w  = (const float*)d_in[2];
    const float* conv_b  = (const float*)d_in[3];
    const float* bbox_w  = (const float*)d_in[4];
    const float* bbox_b  = (const float*)d_in[5];
    const float* score_w = (const float*)d_in[6];
    const float* score_b = (const float*)d_in[7];
    float* out = (float*)d_out;

    // smem: 3 stages x 256*72 halves * 2B = 110592 B (epilogue reuses 67.6 KB of it)
    const int DSMEM = 3 * STG * 2;
    cudaFuncSetAttribute(gemm_hmma, cudaFuncAttributeMaxDynamicSharedMemorySize, DSMEM);

    iou_wconv_kernel<<<IBLK + WBLK, 256>>>(target, conv_w);
    selection_kernel<<<1, 1024>>>();
    gather_kernel<<<(NU2 * 1536) / 256, 256>>>(x);
    gemm_hmma<<<dim3(NU2 / 128, CIN / 128, KSPLIT), 256, DSMEM>>>();
    coldot_loss_kernel<<<NCOL / 8, 256>>>(bbox_w, bbox_b, score_w, score_b,
                                          conv_b, target, out);
}